// round 14
// baseline (speedup 1.0000x reference)
#include <cuda_runtime.h>
#include <cuda_bf16.h>
#include <stdint.h>
#include <math.h>

#define NN 50000
#define EE 800000
#define DIN 128
#define DD 64
#define GG 512
#define TR 128
#define SCALING_F 0.46211715726000974f

// ---------------- scratch ----------------
__device__ __align__(16) float g_x[NN * DD];
__device__ __align__(16) float g_h[NN * DD];
__device__ __align__(16) float g_agg[NN * DD];
__device__ __align__(16) float g_Z[3][NN * DD];
__device__ __align__(16) float g_stats[2 * DD];
__device__ __align__(16) float g_pool[GG * DD];

__device__ __forceinline__ void red_add_v4(float* p, float4 v) {
    asm volatile("red.global.add.v4.f32 [%0], {%1, %2, %3, %4};"
                 :: "l"(p), "f"(v.x), "f"(v.y), "f"(v.z), "f"(v.w) : "memory");
}

// packed convert: result.low = bf16(lo), result.high = bf16(hi)
__device__ __forceinline__ uint32_t bf2(float hi, float lo) {
    uint32_t r;
    asm("cvt.rn.bf16x2.f32 %0, %1, %2;" : "=r"(r) : "f"(hi), "f"(lo));
    return r;
}

// split bf16: h = bf16x2(f0,f1), l = bf16x2 of residuals
__device__ __forceinline__ void pack2(float f0, float f1, uint32_t& h, uint32_t& l) {
    h = bf2(f1, f0);
    float h0 = __uint_as_float(h << 16);
    float h1 = __uint_as_float(h & 0xffff0000u);
    l = bf2(f1 - h1, f0 - h0);
}

__device__ __forceinline__ void mma_bf16(float* d, uint32_t a0, uint32_t a1,
                                         uint32_t a2, uint32_t a3,
                                         uint32_t b0, uint32_t b1) {
    asm volatile("mma.sync.aligned.m16n8k16.row.col.f32.bf16.bf16.f32 "
                 "{%0,%1,%2,%3}, {%4,%5,%6,%7}, {%8,%9}, {%0,%1,%2,%3};"
                 : "+f"(d[0]), "+f"(d[1]), "+f"(d[2]), "+f"(d[3])
                 : "r"(a0), "r"(a1), "r"(a2), "r"(a3), "r"(b0), "r"(b1));
}

// As layout: [wt(8)][kstep(4)][lane(32)][8 u32] = 8192 u32 (32KB)
__device__ __forceinline__ void pack_A(uint32_t* As, int r, int cq, float4 v) {
    int wt = r >> 4;
    int ri = r & 15;
    int k0 = cq * 4;
    int ks = k0 >> 4;
    int ki = k0 & 15;
    int reg = (ri >> 3) + ((ki >> 3) << 1);
    int lane0 = ((ri & 7) << 2) | ((ki >> 1) & 3);
    uint32_t h0, l0, h1, l1;
    pack2(v.x, v.y, h0, l0);
    pack2(v.z, v.w, h1, l1);
    uint32_t* p0 = As + ((wt * 4 + ks) * 32 + lane0) * 8 + reg;
    p0[0] = h0;
    p0[4] = l0;
    p0[8] = h1;
    p0[12] = l1;
}

// Wsp layout: [kstep(4)][nt(8)][lane(32)][4 u32] = 4096 u32 (16KB)
__device__ __forceinline__ void pack_W(uint32_t* Wsp, int k2, int n, float w0, float w1) {
    int ks = k2 >> 3;
    int p = k2 & 7;
    int tid4 = p & 3;
    int bsel = p >> 2;
    int lane = ((n & 7) << 2) | tid4;
    int nt = n >> 3;
    uint32_t h, l;
    pack2(w0, w1, h, l);
    uint32_t* q = Wsp + ((ks * 8 + nt) * 32 + lane) * 4;
    q[bsel] = h;
    q[2 + bsel] = l;
}

// d[8][4] += A(16x64) * W(64x64), 3-term split-bf16
__device__ __forceinline__ void mma_main(const uint32_t* As, const uint32_t* Wsp,
                                         int wid, int lane, float d[8][4]) {
#pragma unroll
    for (int ks = 0; ks < 4; ks++) {
        const uint32_t* ap = As + ((wid * 4 + ks) * 32 + lane) * 8;
        uint4 AH = *(const uint4*)ap;
        uint4 AL = *(const uint4*)(ap + 4);
        const uint32_t* wp = Wsp + (ks * 256 + lane) * 4;
#pragma unroll
        for (int nt = 0; nt < 8; nt++) {
            uint4 B = *(const uint4*)(wp + nt * 128);
            mma_bf16(d[nt], AH.x, AH.y, AH.z, AH.w, B.x, B.y);
            mma_bf16(d[nt], AH.x, AH.y, AH.z, AH.w, B.z, B.w);
            mma_bf16(d[nt], AL.x, AL.y, AL.z, AL.w, B.x, B.y);
        }
    }
}

// accumulators -> tile[128][64] f32 (tile aliases As)
__device__ __forceinline__ void mma_scatter(float* tile, int wid, int lane, float d[8][4]) {
    int g = lane >> 2;
    int tq = lane & 3;
    int r0 = wid * 16 + g;
#pragma unroll
    for (int nt = 0; nt < 8; nt++) {
        int c = nt * 8 + tq * 2;
        *(float2*)&tile[r0 * 64 + c] = make_float2(d[nt][0], d[nt][1]);
        *(float2*)&tile[(r0 + 8) * 64 + c] = make_float2(d[nt][2], d[nt][3]);
    }
}

// ---------------- GEMM 0 ----------------
__global__ __launch_bounds__(256, 3) void k_gemm0(const float* __restrict__ xin,
                                                  const float* __restrict__ W0,
                                                  const float* __restrict__ b0) {
    __shared__ __align__(16) uint32_t As[8192];
    __shared__ __align__(16) uint32_t Wsp[4096];
    float* tile = (float*)As;
    int t = threadIdx.x;
    int lane = t & 31;
    int wid = t >> 5;
    int R0 = blockIdx.x * TR;
    float4 z4 = make_float4(0.f, 0.f, 0.f, 0.f);

    if (blockIdx.x < 32) ((float4*)g_pool)[blockIdx.x * 256u + t] = z4;
    if (blockIdx.x == 0 && t < 128) g_stats[t] = 0.f;

    float d[8][4] = {};
    for (int kb = 0; kb < 128; kb += 64) {
        if (kb) __syncthreads();
#pragma unroll
        for (int i = 0; i < 8; i++) {
            int idx4 = t + i * 256;
            int r = idx4 >> 4;
            int cq = idx4 & 15;
            int gr = R0 + r;
            float4 v = (gr < NN) ? *(const float4*)&xin[gr * 128 + kb + cq * 4] : z4;
            pack_A(As, r, cq, v);
        }
#pragma unroll
        for (int i = 0; i < 8; i++) {
            int pidx = t + i * 256;
            int k2 = pidx >> 6;
            int n = pidx & 63;
            int gk = kb + 2 * k2;
            pack_W(Wsp, k2, n, W0[gk * 64 + n], W0[(gk + 1) * 64 + n]);
        }
        __syncthreads();
        mma_main(As, Wsp, wid, lane, d);
    }
    mma_scatter(tile, wid, lane, d);
    __syncthreads();

    int tx = t & 15;
    int ty = t >> 4;
    int c4 = tx * 4;
    float4 bb = *(const float4*)&b0[c4];
    float o[8][4];
    float pr[8];
#pragma unroll
    for (int r = 0; r < 8; r++) {
        float4 dv = *(const float4*)&tile[(ty * 8 + r) * 64 + c4];
        o[r][0] = fmaxf(dv.x + bb.x, 0.f);
        o[r][1] = fmaxf(dv.y + bb.y, 0.f);
        o[r][2] = fmaxf(dv.z + bb.z, 0.f);
        o[r][3] = fmaxf(dv.w + bb.w, 0.f);
        pr[r] = o[r][0]*o[r][0] + o[r][1]*o[r][1] + o[r][2]*o[r][2] + o[r][3]*o[r][3];
    }
#pragma unroll
    for (int m = 1; m < 16; m <<= 1) {
#pragma unroll
        for (int r = 0; r < 8; r++) pr[r] += __shfl_xor_sync(0xffffffffu, pr[r], m);
    }
#pragma unroll
    for (int r = 0; r < 8; r++) {
        int gr = R0 + ty * 8 + r;
        if (gr < NN) {
            float4 ov = make_float4(o[r][0], o[r][1], o[r][2], o[r][3]);
            *(float4*)&g_x[gr * 64 + c4] = ov;
            *(float4*)&g_agg[gr * 64 + c4] = ov;
            float cn = fmaxf(sqrtf(pr[r]), 1e-15f);
            float f = (cn > 0.996f) ? (0.996f / cn) : 1.0f;
            f *= SCALING_F;
            *(float4*)&g_Z[0][gr * 64 + c4] =
                make_float4(o[r][0]*f, o[r][1]*f, o[r][2]*f, o[r][3]*f);
        }
    }
}

// ---------------- edge scatter ----------------
__global__ void k_edge(const int* __restrict__ ei) {
    unsigned tid = blockIdx.x * 256u + threadIdx.x;
    if (blockIdx.x == 0 && threadIdx.x < 128) g_stats[threadIdx.x] = 0.f;
    unsigned e = tid >> 4;
    unsigned q = tid & 15u;
    int s = __ldg(&ei[e]);
    int dn = __ldg(&ei[EE + e]);
    float4 v = *(const float4*)&g_x[(unsigned)s * 64u + q * 4u];
    red_add_v4(&g_agg[(unsigned)dn * 64u + q * 4u], v);
}

// ---------------- GEMM A (stats buffers alias Wsp after mma) ----------------
__global__ __launch_bounds__(256, 3) void k_gemmA(const float* __restrict__ W,
                                                  const float* __restrict__ b) {
    __shared__ __align__(16) uint32_t As[8192];
    __shared__ __align__(16) uint32_t Wsp[4096];
    float* tile = (float*)As;
    float* s_sum = (float*)Wsp;
    float* s_sq = (float*)Wsp + 64;
    int t = threadIdx.x;
    int lane = t & 31;
    int wid = t >> 5;
    int R0 = blockIdx.x * TR;
    float4 z4 = make_float4(0.f, 0.f, 0.f, 0.f);

#pragma unroll
    for (int i = 0; i < 8; i++) {
        int idx4 = t + i * 256;
        int r = idx4 >> 4;
        int cq = idx4 & 15;
        int gr = R0 + r;
        float4 v = (gr < NN) ? *(const float4*)&g_agg[gr * 64 + cq * 4] : z4;
        pack_A(As, r, cq, v);
    }
#pragma unroll
    for (int i = 0; i < 8; i++) {
        int pidx = t + i * 256;
        int k2 = pidx >> 6;
        int n = pidx & 63;
        pack_W(Wsp, k2, n, W[2 * k2 * 64 + n], W[(2 * k2 + 1) * 64 + n]);
    }
    __syncthreads();
    float d[8][4] = {};
    mma_main(As, Wsp, wid, lane, d);
    mma_scatter(tile, wid, lane, d);
    __syncthreads();
    if (t < 64) { s_sum[t] = 0.f; s_sq[t] = 0.f; }
    __syncthreads();

    int tx = t & 15;
    int ty = t >> 4;
    int c4 = tx * 4;
    float4 bb = *(const float4*)&b[c4];
    float ps[4] = {0.f, 0.f, 0.f, 0.f};
    float pq[4] = {0.f, 0.f, 0.f, 0.f};
#pragma unroll
    for (int i = 0; i < 8; i++) {
        int gr = R0 + ty * 8 + i;
        float4 dv = *(const float4*)&tile[(ty * 8 + i) * 64 + c4];
        float o0 = fmaxf(dv.x + bb.x, 0.f);
        float o1 = fmaxf(dv.y + bb.y, 0.f);
        float o2 = fmaxf(dv.z + bb.z, 0.f);
        float o3 = fmaxf(dv.w + bb.w, 0.f);
        if (gr < NN) {
            *(float4*)&g_h[gr * 64 + c4] = make_float4(o0, o1, o2, o3);
            ps[0] += o0; ps[1] += o1; ps[2] += o2; ps[3] += o3;
            pq[0] += o0*o0; pq[1] += o1*o1; pq[2] += o2*o2; pq[3] += o3*o3;
        }
    }
#pragma unroll
    for (int j = 0; j < 4; j++) {
        atomicAdd(&s_sum[c4 + j], ps[j]);
        atomicAdd(&s_sq[c4 + j], pq[j]);
    }
    __syncthreads();
    if (t < 64) {
        atomicAdd(&g_stats[t], s_sum[t]);
        atomicAdd(&g_stats[64 + t], s_sq[t]);
    }
}

// ---------------- GEMM B + hyperbolic update (2 lanes per row) ----------------
__global__ __launch_bounds__(256, 3) void k_gemmB(const float* __restrict__ W,
                                                  const float* __restrict__ b,
                                                  const float* __restrict__ gamma,
                                                  const float* __restrict__ beta,
                                                  const int* __restrict__ batch,
                                                  int iter, int last) {
    __shared__ __align__(16) uint32_t As[8192];
    __shared__ __align__(16) uint32_t Wsp[4096];
    float* tile = (float*)As;
    int t = threadIdx.x;
    int lane = t & 31;
    int wid = t >> 5;
    int R0 = blockIdx.x * TR;
    int tx = t & 15;
    int ty = t >> 4;
    int c4 = tx * 4;

    // BN affine for this thread's fixed column quad
    float scr[4], shr[4];
#pragma unroll
    for (int j = 0; j < 4; j++) {
        int c = c4 + j;
        float mean = g_stats[c] * (1.0f / NN);
        float var = g_stats[64 + c] * (1.0f / NN) - mean * mean;
        float inv = rsqrtf(var + 1e-5f);
        float s = gamma[c] * inv;
        scr[j] = s;
        shr[j] = beta[c] - mean * s;
    }

#pragma unroll
    for (int i = 0; i < 8; i++) {
        int idx4 = t + i * 256;
        int r = idx4 >> 4;
        int cq = idx4 & 15;
        int gr = R0 + r;
        float4 v;
        if (gr < NN) {
            float4 h = *(const float4*)&g_h[gr * 64 + cq * 4];
            v.x = fmaf(h.x, scr[0], shr[0]);
            v.y = fmaf(h.y, scr[1], shr[1]);
            v.z = fmaf(h.z, scr[2], shr[2]);
            v.w = fmaf(h.w, scr[3], shr[3]);
        } else {
            v = make_float4(0.f, 0.f, 0.f, 0.f);
        }
        pack_A(As, r, cq, v);
    }
#pragma unroll
    for (int i = 0; i < 8; i++) {
        int pidx = t + i * 256;
        int k2 = pidx >> 6;
        int n = pidx & 63;
        pack_W(Wsp, k2, n, W[2 * k2 * 64 + n], W[(2 * k2 + 1) * 64 + n]);
    }
    __syncthreads();
    float d[8][4] = {};
    mma_main(As, Wsp, wid, lane, d);
    mma_scatter(tile, wid, lane, d);
    __syncthreads();

    float4 bb = *(const float4*)&b[c4];
#pragma unroll
    for (int i = 0; i < 8; i++) {
        int r = ty * 8 + i;
        int gr = R0 + r;
        float4 dv = *(const float4*)&tile[r * 64 + c4];
        float4 ov;
        ov.x = fmaxf(dv.x + bb.x, 0.f);
        ov.y = fmaxf(dv.y + bb.y, 0.f);
        ov.z = fmaxf(dv.z + bb.z, 0.f);
        ov.w = fmaxf(dv.w + bb.w, 0.f);
        if (c4 == 60) ov.w = 0.f;    // x[:, -1] = 0
        if (gr < NN) {
            *(float4*)&g_x[gr * 64 + c4] = ov;
            *(float4*)&g_agg[gr * 64 + c4] = ov;
        }
    }
    __syncthreads();   // g_x writes visible block-wide before hyp reads

    // ---- hyperbolic update: 2 lanes per row, chain once per warp ----
    int half = lane & 1;
    int rr = wid * 16 + (lane >> 1);
    int gr = R0 + rr;
    int grc = (gr < NN) ? gr : (NN - 1);
    const float4* xg = (const float4*)&g_x[grc * 64 + half * 32];
    const float4* mcg = (const float4*)&g_Z[iter][grc * 64 + half * 32];
    const float4* ppg = (const float4*)&g_Z[(iter + 2) % 3][grc * 64 + half * 32];
    float4* zng = (float4*)&g_Z[(iter + 1) % 3][grc * 64 + half * 32];

    float d0 = 0.f, d1 = 0.f, d2 = 0.f, d3 = 0.f, d4 = 0.f, d5 = 0.f;
    float mcw = 0.f, ppw = 0.f;
#pragma unroll
    for (int j = 0; j < 8; j++) {
        float4 xv = xg[j];
        float4 mv = mcg[j];
        d0 += xv.x*xv.x + xv.y*xv.y + xv.z*xv.z + xv.w*xv.w;
        d1 += mv.x*mv.x + mv.y*mv.y + mv.z*mv.z + mv.w*mv.w;
        d5 += mv.x*xv.x + mv.y*xv.y + mv.z*xv.z + mv.w*xv.w;
        if (j == 7) mcw = mv.w;
        if (iter) {
            float4 pv = ppg[j];
            d2 += pv.x*pv.x + pv.y*pv.y + pv.z*pv.z + pv.w*pv.w;
            d3 += pv.x*mv.x + pv.y*mv.y + pv.z*mv.z + pv.w*mv.w;
            d4 += pv.x*xv.x + pv.y*xv.y + pv.z*xv.z + pv.w*xv.w;
            if (j == 7) ppw = pv.w;
        }
    }
    d0 += __shfl_xor_sync(0xffffffffu, d0, 1);
    d1 += __shfl_xor_sync(0xffffffffu, d1, 1);
    d5 += __shfl_xor_sync(0xffffffffu, d5, 1);
    if (iter) {
        d2 += __shfl_xor_sync(0xffffffffu, d2, 1);
        d3 += __shfl_xor_sync(0xffffffffu, d3, 1);
        d4 += __shfl_xor_sync(0xffffffffu, d4, 1);
    }
    float mc63 = __shfl_sync(0xffffffffu, mcw, lane | 1);
    float pp63 = iter ? __shfl_sync(0xffffffffu, ppw, lane | 1) : 0.f;

    // closed-form chain: zn = cx*x + cpp*pp + cmm*mc + ce*e63
    float cn = fmaxf(sqrtf(d0), 1e-15f);
    float f = (cn > 0.996f) ? (0.996f / cn) : 1.0f;
    f *= SCALING_F;
    float mn2 = fmaxf(d1, 1e-15f);
    float im = 1.0f / mn2;
    float a2 = d1 * im * im;
    float r2 = a2 - 1.0f;
    float un2 = fmaxf(d2 - 2.0f*d3*im + a2, 1e-15f);
    float s1 = r2 / un2;
    float t1 = 1.0f - s1;
    float zpn2 = s1*s1*d2 + 2.0f*s1*t1*d3*im + t1*t1*a2;
    float pn = fmaxf(sqrtf(zpn2), 1e-15f);
    float zpzc = f * (s1*d4 + t1*d5*im);
    float zp63 = s1*pp63 + t1*mc63*im;
    float mnum = -zpzc / pn;
    float mden = 2.0f - 2.0f*zp63/pn;
    float mm = mnum / mden;
    float gg = 2.0f*mm/pn;
    float zcc2 = f*f*d0 + gg*gg*zpn2 + 4.0f*mm*mm + 2.0f*gg*zpzc - 4.0f*mm*gg*zp63;
    float zca = f*d5*im;
    float zpa = s1*d3*im + t1*a2;
    float zcca = zca + gg*zpa - 2.0f*mm*mc63*im;
    float u2n = fmaxf(zcc2 - 2.0f*zcca + a2, 1e-15f);
    float s2 = r2 / u2n;
    float t2 = 1.0f - s2;
    float cx = s2*f;
    float cpp = s2*gg*s1;
    float cmm = (s2*gg*t1 + t2)*im;
    float ce = -2.0f*mm*s2;

    float sc = 0.f;
    int bg = 0;
    if (last) {
        float znn2 = s2*s2*zcc2 + 2.0f*s2*t2*zcca + t2*t2*a2;
        float yn = fmaxf(sqrtf(fmaxf(znn2, 0.f)), 1e-15f);
        float tt = fminf(yn, 1.0f);
        sc = atanhf(tt) / yn;
        bg = __ldg(&batch[grc]);
    }

#pragma unroll
    for (int j = 0; j < 8; j++) {
        float4 xv = xg[j];
        float4 mv = mcg[j];
        float4 zn;
        zn.x = cx*xv.x + cmm*mv.x;
        zn.y = cx*xv.y + cmm*mv.y;
        zn.z = cx*xv.z + cmm*mv.z;
        zn.w = cx*xv.w + cmm*mv.w;
        if (iter) {
            float4 pv = ppg[j];
            zn.x += cpp*pv.x;
            zn.y += cpp*pv.y;
            zn.z += cpp*pv.z;
            zn.w += cpp*pv.w;
        }
        if (half == 1 && j == 7) zn.w += ce;
        if (gr < NN) {
            zng[j] = zn;
            if (last) {
                red_add_v4(&g_pool[bg * 64 + half * 32 + j * 4],
                           make_float4(zn.x*sc, zn.y*sc, zn.z*sc, zn.w*sc));
            }
        }
    }
}

// ---------------- head MLP + log_softmax ----------------
__global__ void k_head(const float* __restrict__ fc1W, const float* __restrict__ fc1b,
                       const float* __restrict__ fc2W, const float* __restrict__ fc2b,
                       const float* __restrict__ fc3W, const float* __restrict__ fc3b,
                       float* __restrict__ out) {
    __shared__ float sp[64];
    __shared__ float h1[128];
    __shared__ float h2[64];
    __shared__ float lo[10];
    int g = blockIdx.x;
    int t = threadIdx.x;
    if (t < 64) sp[t] = g_pool[g * 64 + t];
    __syncthreads();
    {
        float acc = fc1b[t];
#pragma unroll 8
        for (int k = 0; k < 64; k++) acc = fmaf(sp[k], fc1W[k * 128 + t], acc);
        h1[t] = fmaxf(acc, 0.f);
    }
    __syncthreads();
    if (t < 64) {
        float acc = fc2b[t];
#pragma unroll 8
        for (int k = 0; k < 128; k++) acc = fmaf(h1[k], fc2W[k * 64 + t], acc);
        h2[t] = fmaxf(acc, 0.f);
    }
    __syncthreads();
    if (t < 10) {
        float acc = fc3b[t];
#pragma unroll 8
        for (int k = 0; k < 64; k++) acc = fmaf(h2[k], fc3W[k * 10 + t], acc);
        lo[t] = acc;
    }
    __syncthreads();
    if (t == 0) {
        float mx = lo[0];
#pragma unroll
        for (int c = 1; c < 10; c++) mx = fmaxf(mx, lo[c]);
        float s = 0.f;
#pragma unroll
        for (int c = 0; c < 10; c++) s += expf(lo[c] - mx);
        float lse = mx + logf(s);
#pragma unroll
        for (int c = 0; c < 10; c++) out[g * 10 + c] = lo[c] - lse;
    }
}

// ---------------- launch ----------------
extern "C" void kernel_launch(void* const* d_in, const int* in_sizes, int n_in,
                              void* d_out, int out_size) {
    const float* x     = (const float*)d_in[0];
    const int*   ei    = (const int*)d_in[1];
    const int*   batch = (const int*)d_in[2];
    const float* W0    = (const float*)d_in[3];
    const float* b0    = (const float*)d_in[4];
    const float* cW1   = (const float*)d_in[5];
    const float* cb1   = (const float*)d_in[6];
    const float* gamma = (const float*)d_in[7];
    const float* beta  = (const float*)d_in[8];
    const float* cW2   = (const float*)d_in[9];
    const float* cb2   = (const float*)d_in[10];
    const float* fc1W  = (const float*)d_in[11];
    const float* fc1b  = (const float*)d_in[12];
    const float* fc2W  = (const float*)d_in[13];
    const float* fc2b  = (const float*)d_in[14];
    const float* fc3W  = (const float*)d_in[15];
    const float* fc3b  = (const float*)d_in[16];
    float* out = (float*)d_out;

    const int gemmGrid = (NN + TR - 1) / TR;     // 391
    const int edgeGrid = (EE * 16) / 256;        // 50000

    k_gemm0<<<gemmGrid, 256>>>(x, W0, b0);
    for (int l = 0; l < 3; l++) {
        k_edge<<<edgeGrid, 256>>>(ei);
        k_gemmA<<<gemmGrid, 256>>>(cW1 + l * 64 * 64, cb1 + l * 64);
        k_gemmB<<<gemmGrid, 256>>>(cW2 + l * 64 * 64, cb2 + l * 64,
                                   gamma + l * 64, beta + l * 64,
                                   batch, l, (l == 2) ? 1 : 0);
    }
    k_head<<<512, 128>>>(fc1W, fc1b, fc2W, fc2b, fc3W, fc3b, out);
}

// round 16
// speedup vs baseline: 1.2140x; 1.2140x over previous
#include <cuda_runtime.h>
#include <cuda_bf16.h>
#include <stdint.h>
#include <math.h>

#define NN 50000
#define EE 800000
#define DIN 128
#define DD 64
#define GG 512
#define TR 128
#define NB 98               // scan blocks = ceil(NN/512)
#define SCALING_F 0.46211715726000974f

// ---------------- scratch ----------------
__device__ __align__(16) float g_x[NN * DD];
__device__ __align__(16) float g_h[NN * DD];
__device__ __align__(16) float g_agg[NN * DD];
__device__ __align__(16) float g_Z[3][NN * DD];
__device__ __align__(16) float g_stats[2 * DD];
__device__ __align__(16) float g_pool[GG * DD];
// CSR scratch
__device__ int g_cnt[NN];
__device__ int g_sc[NN];
__device__ int g_bsum[128];
__device__ int g_off[NN + 1];
__device__ int g_cur[NN];
__device__ int g_csr[EE];

__device__ __forceinline__ void red_add_v2(float* p, float a, float b) {
    asm volatile("red.global.add.v2.f32 [%0], {%1, %2};"
                 :: "l"(p), "f"(a), "f"(b) : "memory");
}

// split bf16: h = bf16(f), l = bf16(f - h); packed as bf16x2
__device__ __forceinline__ void pack2(float f0, float f1, uint32_t& h, uint32_t& l) {
    __nv_bfloat162 hb;
    hb.x = __float2bfloat16_rn(f0);
    hb.y = __float2bfloat16_rn(f1);
    __nv_bfloat162 lb;
    lb.x = __float2bfloat16_rn(f0 - __bfloat162float(hb.x));
    lb.y = __float2bfloat16_rn(f1 - __bfloat162float(hb.y));
    h = *reinterpret_cast<uint32_t*>(&hb);
    l = *reinterpret_cast<uint32_t*>(&lb);
}

__device__ __forceinline__ void mma_bf16(float* d, uint32_t a0, uint32_t a1,
                                         uint32_t a2, uint32_t a3,
                                         uint32_t b0, uint32_t b1) {
    asm volatile("mma.sync.aligned.m16n8k16.row.col.f32.bf16.bf16.f32 "
                 "{%0,%1,%2,%3}, {%4,%5,%6,%7}, {%8,%9}, {%0,%1,%2,%3};"
                 : "+f"(d[0]), "+f"(d[1]), "+f"(d[2]), "+f"(d[3])
                 : "r"(a0), "r"(a1), "r"(a2), "r"(a3), "r"(b0), "r"(b1));
}

// As layout: [wt(8)][kstep(4)][lane(32)][8 u32] = 8192 u32 (32KB)
__device__ __forceinline__ void pack_A(uint32_t* As, int r, int cq, float4 v) {
    int wt = r >> 4;
    int ri = r & 15;
    int k0 = cq * 4;
    int ks = k0 >> 4;
    int ki = k0 & 15;
    int reg = (ri >> 3) + ((ki >> 3) << 1);
    int lane0 = ((ri & 7) << 2) | ((ki >> 1) & 3);
    uint32_t h0, l0, h1, l1;
    pack2(v.x, v.y, h0, l0);
    pack2(v.z, v.w, h1, l1);
    uint32_t* p0 = As + ((wt * 4 + ks) * 32 + lane0) * 8 + reg;
    p0[0] = h0;
    p0[4] = l0;
    p0[8] = h1;
    p0[12] = l1;
}

// Wsp layout: [kstep(4)][nt(8)][lane(32)][4 u32] = 4096 u32 (16KB)
__device__ __forceinline__ void pack_W(uint32_t* Wsp, int k2, int n, float w0, float w1) {
    int ks = k2 >> 3;
    int p = k2 & 7;
    int tid4 = p & 3;
    int bsel = p >> 2;
    int lane = ((n & 7) << 2) | tid4;
    int nt = n >> 3;
    uint32_t h, l;
    pack2(w0, w1, h, l);
    uint32_t* q = Wsp + ((ks * 8 + nt) * 32 + lane) * 4;
    q[bsel] = h;
    q[2 + bsel] = l;
}

// d[8][4] += A(16x64) * W(64x64), 3-term split-bf16
__device__ __forceinline__ void mma_main(const uint32_t* As, const uint32_t* Wsp,
                                         int wid, int lane, float d[8][4]) {
#pragma unroll
    for (int ks = 0; ks < 4; ks++) {
        const uint32_t* ap = As + ((wid * 4 + ks) * 32 + lane) * 8;
        uint4 AH = *(const uint4*)ap;
        uint4 AL = *(const uint4*)(ap + 4);
        const uint32_t* wp = Wsp + (ks * 256 + lane) * 4;
#pragma unroll
        for (int nt = 0; nt < 8; nt++) {
            uint4 B = *(const uint4*)(wp + nt * 128);
            mma_bf16(d[nt], AH.x, AH.y, AH.z, AH.w, B.x, B.y);
            mma_bf16(d[nt], AH.x, AH.y, AH.z, AH.w, B.z, B.w);
            mma_bf16(d[nt], AL.x, AL.y, AL.z, AL.w, B.x, B.y);
        }
    }
}

// accumulators -> tile[128][64] f32 (tile aliases As)
__device__ __forceinline__ void mma_scatter(float* tile, int wid, int lane, float d[8][4]) {
    int g = lane >> 2;
    int tq = lane & 3;
    int r0 = wid * 16 + g;
#pragma unroll
    for (int nt = 0; nt < 8; nt++) {
        int c = nt * 8 + tq * 2;
        *(float2*)&tile[r0 * 64 + c] = make_float2(d[nt][0], d[nt][1]);
        *(float2*)&tile[(r0 + 8) * 64 + c] = make_float2(d[nt][2], d[nt][3]);
    }
}

// ---------------- GEMM 0 (also zeros pool/stats/cnt) ----------------
__global__ __launch_bounds__(256, 3) void k_gemm0(const float* __restrict__ xin,
                                                  const float* __restrict__ W0,
                                                  const float* __restrict__ b0) {
    __shared__ __align__(16) uint32_t As[8192];
    __shared__ __align__(16) uint32_t Wsp[4096];
    float* tile = (float*)As;
    int t = threadIdx.x;
    int lane = t & 31;
    int wid = t >> 5;
    int R0 = blockIdx.x * TR;
    float4 z4 = make_float4(0.f, 0.f, 0.f, 0.f);

    if (blockIdx.x < 32) ((float4*)g_pool)[blockIdx.x * 256u + t] = z4;
    if (blockIdx.x == 0 && t < 128) g_stats[t] = 0.f;
    {
        int ci = blockIdx.x * 256 + t;
        if (ci < NN) g_cnt[ci] = 0;
    }

    float d[8][4] = {};
    for (int kb = 0; kb < 128; kb += 64) {
        if (kb) __syncthreads();
#pragma unroll
        for (int i = 0; i < 8; i++) {
            int idx4 = t + i * 256;
            int r = idx4 >> 4;
            int cq = idx4 & 15;
            int gr = R0 + r;
            float4 v = (gr < NN) ? *(const float4*)&xin[gr * 128 + kb + cq * 4] : z4;
            pack_A(As, r, cq, v);
        }
#pragma unroll
        for (int i = 0; i < 8; i++) {
            int pidx = t + i * 256;
            int k2 = pidx >> 6;
            int n = pidx & 63;
            int gk = kb + 2 * k2;
            pack_W(Wsp, k2, n, W0[gk * 64 + n], W0[(gk + 1) * 64 + n]);
        }
        __syncthreads();
        mma_main(As, Wsp, wid, lane, d);
    }
    mma_scatter(tile, wid, lane, d);
    __syncthreads();

    int tx = t & 15;
    int ty = t >> 4;
    int c4 = tx * 4;
    float4 bb = *(const float4*)&b0[c4];
    float o[8][4];
    float pr[8];
#pragma unroll
    for (int r = 0; r < 8; r++) {
        float4 dv = *(const float4*)&tile[(ty * 8 + r) * 64 + c4];
        o[r][0] = fmaxf(dv.x + bb.x, 0.f);
        o[r][1] = fmaxf(dv.y + bb.y, 0.f);
        o[r][2] = fmaxf(dv.z + bb.z, 0.f);
        o[r][3] = fmaxf(dv.w + bb.w, 0.f);
        pr[r] = o[r][0]*o[r][0] + o[r][1]*o[r][1] + o[r][2]*o[r][2] + o[r][3]*o[r][3];
    }
#pragma unroll
    for (int m = 1; m < 16; m <<= 1) {
#pragma unroll
        for (int r = 0; r < 8; r++) pr[r] += __shfl_xor_sync(0xffffffffu, pr[r], m);
    }
#pragma unroll
    for (int r = 0; r < 8; r++) {
        int gr = R0 + ty * 8 + r;
        if (gr < NN) {
            float4 ov = make_float4(o[r][0], o[r][1], o[r][2], o[r][3]);
            *(float4*)&g_x[gr * 64 + c4] = ov;
            float cn = fmaxf(sqrtf(pr[r]), 1e-15f);
            float f = (cn > 0.996f) ? (0.996f / cn) : 1.0f;
            f *= SCALING_F;
            *(float4*)&g_Z[0][gr * 64 + c4] =
                make_float4(o[r][0]*f, o[r][1]*f, o[r][2]*f, o[r][3]*f);
        }
    }
}

// ---------------- CSR build ----------------
__global__ void k_hist(const int* __restrict__ ei) {
    unsigned e = blockIdx.x * 256u + threadIdx.x;
    if (e < EE) atomicAdd(&g_cnt[__ldg(&ei[EE + e])], 1);
}

__global__ void k_scan1() {
    __shared__ int ws[16];
    int t = threadIdx.x;
    int b = blockIdx.x;
    int i = b * 512 + t;
    int lane = t & 31;
    int w = t >> 5;
    int x = (i < NN) ? g_cnt[i] : 0;
#pragma unroll
    for (int o = 1; o < 32; o <<= 1) {
        int y = __shfl_up_sync(0xffffffffu, x, o);
        if (lane >= o) x += y;
    }
    if (lane == 31) ws[w] = x;
    __syncthreads();
    if (w == 0) {
        int s = (lane < 16) ? ws[lane] : 0;
#pragma unroll
        for (int o = 1; o < 16; o <<= 1) {
            int y = __shfl_up_sync(0xffffffffu, s, o);
            if (lane >= o) s += y;
        }
        if (lane < 16) ws[lane] = s;
    }
    __syncthreads();
    int incl = x + (w ? ws[w - 1] : 0);
    if (i < NN) g_sc[i] = incl;
    if (t == 511) g_bsum[b] = incl;
}

__global__ void k_scan2() {
    __shared__ int ws[4];
    int t = threadIdx.x;
    int lane = t & 31;
    int w = t >> 5;
    int x = (t < NB) ? g_bsum[t] : 0;
#pragma unroll
    for (int o = 1; o < 32; o <<= 1) {
        int y = __shfl_up_sync(0xffffffffu, x, o);
        if (lane >= o) x += y;
    }
    if (lane == 31) ws[w] = x;
    __syncthreads();
    if (w == 0 && lane < 4) {
        int s = ws[lane];
#pragma unroll
        for (int o = 1; o < 4; o <<= 1) {
            int y = __shfl_up_sync(0x0000000fu, s, o);
            if (lane >= o) s += y;
        }
        ws[lane] = s;
    }
    __syncthreads();
    int incl = x + (w ? ws[w - 1] : 0);
    if (t < NB) g_bsum[t] = incl;
}

__global__ void k_scan3() {
    int b = blockIdx.x;
    int i = b * 512 + threadIdx.x;
    if (i < NN) {
        int base = (b > 0) ? g_bsum[b - 1] : 0;
        int incl = g_sc[i] + base;
        g_off[i + 1] = incl;
        g_cur[i] = incl - g_cnt[i];
        if (i == 0) g_off[0] = 0;
    }
}

__global__ void k_fill(const int* __restrict__ ei) {
    unsigned e = blockIdx.x * 256u + threadIdx.x;
    if (e < EE) {
        int dd = __ldg(&ei[EE + e]);
        int ss = __ldg(&ei[e]);
        int slot = atomicAdd(&g_cur[dd], 1);
        g_csr[slot] = ss;
    }
}

// ---------------- gather: agg[d] = x[d] + sum_{s in N(d)} x[s] ----------------
__global__ __launch_bounds__(256, 8) void k_gather() {
    int t = threadIdx.x;
    if (blockIdx.x == 0 && t < 128) g_stats[t] = 0.f;
    int gw = (blockIdx.x * 256 + t) >> 5;
    if (gw >= NN) return;
    int lane = t & 31;
    int q = lane & 15;
    int grp = lane >> 4;
    int o0 = g_off[gw];
    int o1 = g_off[gw + 1];
    float4 acc = make_float4(0.f, 0.f, 0.f, 0.f);
#pragma unroll 2
    for (int j = o0 + grp; j < o1; j += 2) {
        int s = __ldg(&g_csr[j]);
        float4 v = *(const float4*)&g_x[(unsigned)s * 64u + q * 4u];
        acc.x += v.x;
        acc.y += v.y;
        acc.z += v.z;
        acc.w += v.w;
    }
    acc.x += __shfl_xor_sync(0xffffffffu, acc.x, 16);
    acc.y += __shfl_xor_sync(0xffffffffu, acc.y, 16);
    acc.z += __shfl_xor_sync(0xffffffffu, acc.z, 16);
    acc.w += __shfl_xor_sync(0xffffffffu, acc.w, 16);
    if (lane < 16) {
        float4 xv = *(const float4*)&g_x[(unsigned)gw * 64u + q * 4u];
        *(float4*)&g_agg[(unsigned)gw * 64u + q * 4u] =
            make_float4(xv.x + acc.x, xv.y + acc.y, xv.z + acc.z, xv.w + acc.w);
    }
}

// ---------------- GEMM A (stats buffers alias Wsp after mma) ----------------
__global__ __launch_bounds__(256, 3) void k_gemmA(const float* __restrict__ W,
                                                  const float* __restrict__ b) {
    __shared__ __align__(16) uint32_t As[8192];
    __shared__ __align__(16) uint32_t Wsp[4096];
    float* tile = (float*)As;
    float* s_sum = (float*)Wsp;
    float* s_sq = (float*)Wsp + 64;
    int t = threadIdx.x;
    int lane = t & 31;
    int wid = t >> 5;
    int R0 = blockIdx.x * TR;
    float4 z4 = make_float4(0.f, 0.f, 0.f, 0.f);

#pragma unroll
    for (int i = 0; i < 8; i++) {
        int idx4 = t + i * 256;
        int r = idx4 >> 4;
        int cq = idx4 & 15;
        int gr = R0 + r;
        float4 v = (gr < NN) ? *(const float4*)&g_agg[gr * 64 + cq * 4] : z4;
        pack_A(As, r, cq, v);
    }
#pragma unroll
    for (int i = 0; i < 8; i++) {
        int pidx = t + i * 256;
        int k2 = pidx >> 6;
        int n = pidx & 63;
        pack_W(Wsp, k2, n, W[2 * k2 * 64 + n], W[(2 * k2 + 1) * 64 + n]);
    }
    __syncthreads();
    float d[8][4] = {};
    mma_main(As, Wsp, wid, lane, d);
    mma_scatter(tile, wid, lane, d);
    __syncthreads();
    if (t < 64) { s_sum[t] = 0.f; s_sq[t] = 0.f; }
    __syncthreads();

    int tx = t & 15;
    int ty = t >> 4;
    int c4 = tx * 4;
    float4 bb = *(const float4*)&b[c4];
    float ps[4] = {0.f, 0.f, 0.f, 0.f};
    float pq[4] = {0.f, 0.f, 0.f, 0.f};
#pragma unroll
    for (int i = 0; i < 8; i++) {
        int gr = R0 + ty * 8 + i;
        float4 dv = *(const float4*)&tile[(ty * 8 + i) * 64 + c4];
        float o0 = fmaxf(dv.x + bb.x, 0.f);
        float o1 = fmaxf(dv.y + bb.y, 0.f);
        float o2 = fmaxf(dv.z + bb.z, 0.f);
        float o3 = fmaxf(dv.w + bb.w, 0.f);
        if (gr < NN) {
            *(float4*)&g_h[gr * 64 + c4] = make_float4(o0, o1, o2, o3);
            ps[0] += o0; ps[1] += o1; ps[2] += o2; ps[3] += o3;
            pq[0] += o0*o0; pq[1] += o1*o1; pq[2] += o2*o2; pq[3] += o3*o3;
        }
    }
#pragma unroll
    for (int j = 0; j < 4; j++) {
        atomicAdd(&s_sum[c4 + j], ps[j]);
        atomicAdd(&s_sq[c4 + j], pq[j]);
    }
    __syncthreads();
    if (t < 64) {
        atomicAdd(&g_stats[t], s_sum[t]);
        atomicAdd(&g_stats[64 + t], s_sq[t]);
    }
}

// ---------------- GEMM B + hyperbolic update (BN affine in registers) ----------------
__global__ __launch_bounds__(256, 3) void k_gemmB(const float* __restrict__ W,
                                                  const float* __restrict__ b,
                                                  const float* __restrict__ gamma,
                                                  const float* __restrict__ beta,
                                                  const int* __restrict__ batch,
                                                  int iter, int last) {
    __shared__ __align__(16) uint32_t As[8192];
    __shared__ __align__(16) uint32_t Wsp[4096];
    float* tile = (float*)As;
    int t = threadIdx.x;
    int lane = t & 31;
    int wid = t >> 5;
    int R0 = blockIdx.x * TR;
    int tx = t & 15;
    int ty = t >> 4;
    int c4 = tx * 4;

    float scr[4], shr[4];
#pragma unroll
    for (int j = 0; j < 4; j++) {
        int c = c4 + j;
        float mean = g_stats[c] * (1.0f / NN);
        float var = g_stats[64 + c] * (1.0f / NN) - mean * mean;
        float inv = rsqrtf(var + 1e-5f);
        float s = gamma[c] * inv;
        scr[j] = s;
        shr[j] = beta[c] - mean * s;
    }

#pragma unroll
    for (int i = 0; i < 8; i++) {
        int idx4 = t + i * 256;
        int r = idx4 >> 4;
        int cq = idx4 & 15;
        int gr = R0 + r;
        float4 v;
        if (gr < NN) {
            float4 h = *(const float4*)&g_h[gr * 64 + cq * 4];
            v.x = fmaf(h.x, scr[0], shr[0]);
            v.y = fmaf(h.y, scr[1], shr[1]);
            v.z = fmaf(h.z, scr[2], shr[2]);
            v.w = fmaf(h.w, scr[3], shr[3]);
        } else {
            v = make_float4(0.f, 0.f, 0.f, 0.f);
        }
        pack_A(As, r, cq, v);
    }
#pragma unroll
    for (int i = 0; i < 8; i++) {
        int pidx = t + i * 256;
        int k2 = pidx >> 6;
        int n = pidx & 63;
        pack_W(Wsp, k2, n, W[2 * k2 * 64 + n], W[(2 * k2 + 1) * 64 + n]);
    }
    __syncthreads();
    float d[8][4] = {};
    mma_main(As, Wsp, wid, lane, d);
    mma_scatter(tile, wid, lane, d);
    __syncthreads();

    float4 bb = *(const float4*)&b[c4];
#pragma unroll
    for (int i = 0; i < 8; i++) {
        int r = ty * 8 + i;
        int gr = R0 + r;
        float4 dv = *(const float4*)&tile[r * 64 + c4];
        float4 ov;
        ov.x = fmaxf(dv.x + bb.x, 0.f);
        ov.y = fmaxf(dv.y + bb.y, 0.f);
        ov.z = fmaxf(dv.z + bb.z, 0.f);
        ov.w = fmaxf(dv.w + bb.w, 0.f);
        if (c4 == 60) ov.w = 0.f;    // x[:, -1] = 0
        *(float4*)&tile[r * 64 + c4] = ov;
        if (gr < NN) {
            *(float4*)&g_x[gr * 64 + c4] = ov;
        }
    }
    __syncthreads();

    // hyperbolic update, closed form: zn = cx*x + cpp*pp + cmm*mc + ce*e63
    const float2* zc2 = (const float2*)g_Z[iter];
    const float2* zp2 = (const float2*)g_Z[(iter + 2) % 3];
    float2* zn2 = (float2*)g_Z[(iter + 1) % 3];

    for (int i = 0; i < 16; i++) {
        int rr = wid * 16 + i;
        int gr = R0 + rr;
        if (gr >= NN) break;
        int off = gr * 32 + lane;
        float2 xv = *(const float2*)&tile[rr * 64 + lane * 2];
        float2 mc = zc2[off];
        float2 pp = (iter == 0) ? make_float2(0.f, 0.f) : zp2[off];

        float d0 = xv.x*xv.x + xv.y*xv.y;
        float d1 = mc.x*mc.x + mc.y*mc.y;
        float d2 = pp.x*pp.x + pp.y*pp.y;
        float d3 = pp.x*mc.x + pp.y*mc.y;
        float d4 = pp.x*xv.x + pp.y*xv.y;
        float d5 = mc.x*xv.x + mc.y*xv.y;
#pragma unroll
        for (int o = 16; o; o >>= 1) {
            d0 += __shfl_xor_sync(0xffffffffu, d0, o);
            d1 += __shfl_xor_sync(0xffffffffu, d1, o);
            d2 += __shfl_xor_sync(0xffffffffu, d2, o);
            d3 += __shfl_xor_sync(0xffffffffu, d3, o);
            d4 += __shfl_xor_sync(0xffffffffu, d4, o);
            d5 += __shfl_xor_sync(0xffffffffu, d5, o);
        }
        float mc63 = __shfl_sync(0xffffffffu, mc.y, 31);
        float pp63 = __shfl_sync(0xffffffffu, pp.y, 31);

        float cn = fmaxf(sqrtf(d0), 1e-15f);
        float f = (cn > 0.996f) ? (0.996f / cn) : 1.0f;
        f *= SCALING_F;
        float mn2 = fmaxf(d1, 1e-15f);
        float im = 1.0f / mn2;
        float a2 = d1 * im * im;
        float r2 = a2 - 1.0f;
        float un2 = fmaxf(d2 - 2.0f*d3*im + a2, 1e-15f);
        float s1 = r2 / un2;
        float t1 = 1.0f - s1;
        float zpn2 = s1*s1*d2 + 2.0f*s1*t1*d3*im + t1*t1*a2;
        float pn = fmaxf(sqrtf(zpn2), 1e-15f);
        float zpzc = f * (s1*d4 + t1*d5*im);
        float zp63 = s1*pp63 + t1*mc63*im;
        float mnum = -zpzc / pn;
        float mden = 2.0f - 2.0f*zp63/pn;
        float mm = mnum / mden;
        float gg = 2.0f*mm/pn;
        float zcc2 = f*f*d0 + gg*gg*zpn2 + 4.0f*mm*mm + 2.0f*gg*zpzc - 4.0f*mm*gg*zp63;
        float zca = f*d5*im;
        float zpa = s1*d3*im + t1*a2;
        float zcca = zca + gg*zpa - 2.0f*mm*mc63*im;
        float u2n = fmaxf(zcc2 - 2.0f*zcca + a2, 1e-15f);
        float s2 = r2 / u2n;
        float t2 = 1.0f - s2;
        float cx = s2*f;
        float cpp = s2*gg*s1;
        float cmm = (s2*gg*t1 + t2)*im;
        float ce = -2.0f*mm*s2;

        float znx = cx*xv.x + cpp*pp.x + cmm*mc.x;
        float zny = cx*xv.y + cpp*pp.y + cmm*mc.y;
        if (lane == 31) zny += ce;
        zn2[off] = make_float2(znx, zny);

        if (last) {
            float znn2 = s2*s2*zcc2 + 2.0f*s2*t2*zcca + t2*t2*a2;
            float yn = fmaxf(sqrtf(fmaxf(znn2, 0.f)), 1e-15f);
            float tt = fminf(yn, 1.0f);
            float sc = atanhf(tt) / yn;
            int bg = __ldg(&batch[gr]);
            red_add_v2(&g_pool[bg * 64 + lane * 2], znx * sc, zny * sc);
        }
    }
}

// ---------------- head MLP + log_softmax ----------------
__global__ void k_head(const float* __restrict__ fc1W, const float* __restrict__ fc1b,
                       const float* __restrict__ fc2W, const float* __restrict__ fc2b,
                       const float* __restrict__ fc3W, const float* __restrict__ fc3b,
                       float* __restrict__ out) {
    __shared__ float sp[64];
    __shared__ float h1[128];
    __shared__ float h2[64];
    __shared__ float lo[10];
    int g = blockIdx.x;
    int t = threadIdx.x;
    if (t < 64) sp[t] = g_pool[g * 64 + t];
    __syncthreads();
    {
        float acc = fc1b[t];
#pragma unroll 8
        for (int k = 0; k < 64; k++) acc = fmaf(sp[k], fc1W[k * 128 + t], acc);
        h1[t] = fmaxf(acc, 0.f);
    }
    __syncthreads();
    if (t < 64) {
        float acc = fc2b[t];
#pragma unroll 8
        for (int k = 0; k < 128; k++) acc = fmaf(h1[k], fc2W[k * 64 + t], acc);
        h2[t] = fmaxf(acc, 0.f);
    }
    __syncthreads();
    if (t < 10) {
        float acc = fc3b[t];
#pragma unroll 8
        for (int k = 0; k < 64; k++) acc = fmaf(h2[k], fc3W[k * 10 + t], acc);
        lo[t] = acc;
    }
    __syncthreads();
    if (t == 0) {
        float mx = lo[0];
#pragma unroll
        for (int c = 1; c < 10; c++) mx = fmaxf(mx, lo[c]);
        float s = 0.f;
#pragma unroll
        for (int c = 0; c < 10; c++) s += expf(lo[c] - mx);
        float lse = mx + logf(s);
#pragma unroll
        for (int c = 0; c < 10; c++) out[g * 10 + c] = lo[c] - lse;
    }
}

// ---------------- launch ----------------
extern "C" void kernel_launch(void* const* d_in, const int* in_sizes, int n_in,
                              void* d_out, int out_size) {
    const float* x     = (const float*)d_in[0];
    const int*   ei    = (const int*)d_in[1];
    const int*   batch = (const int*)d_in[2];
    const float* W0    = (const float*)d_in[3];
    const float* b0    = (const float*)d_in[4];
    const float* cW1   = (const float*)d_in[5];
    const float* cb1   = (const float*)d_in[6];
    const float* gamma = (const float*)d_in[7];
    const float* beta  = (const float*)d_in[8];
    const float* cW2   = (const float*)d_in[9];
    const float* cb2   = (const float*)d_in[10];
    const float* fc1W  = (const float*)d_in[11];
    const float* fc1b  = (const float*)d_in[12];
    const float* fc2W  = (const float*)d_in[13];
    const float* fc2b  = (const float*)d_in[14];
    const float* fc3W  = (const float*)d_in[15];
    const float* fc3b  = (const float*)d_in[16];
    float* out = (float*)d_out;

    const int gemmGrid = (NN + TR - 1) / TR;        // 391
    const int eGrid = (EE + 255) / 256;             // 3125
    const int gatherGrid = (NN * 32 + 255) / 256;   // 6250

    k_gemm0<<<gemmGrid, 256>>>(x, W0, b0);
    k_hist<<<eGrid, 256>>>(ei);
    k_scan1<<<NB, 512>>>();
    k_scan2<<<1, 128>>>();
    k_scan3<<<NB, 512>>>();
    k_fill<<<eGrid, 256>>>(ei);
    for (int l = 0; l < 3; l++) {
        k_gather<<<gatherGrid, 256>>>();
        k_gemmA<<<gemmGrid, 256>>>(cW1 + l * 64 * 64, cb1 + l * 64);
        k_gemmB<<<gemmGrid, 256>>>(cW2 + l * 64 * 64, cb2 + l * 64,
                                   gamma + l * 64, beta + l * 64,
                                   batch, l, (l == 2) ? 1 : 0);
    }
    k_head<<<512, 128>>>(fc1W, fc1b, fc2W, fc2b, fc3W, fc3b, out);
}

// round 17
// speedup vs baseline: 1.2524x; 1.0316x over previous
#include <cuda_runtime.h>
#include <cuda_bf16.h>
#include <stdint.h>
#include <math.h>

#define NN 50000
#define EE 800000
#define DIN 128
#define DD 64
#define GG 512
#define TR 128
#define NB 98               // scan blocks = ceil(NN/512)
#define SCALING_F 0.46211715726000974f

// ---------------- scratch ----------------
__device__ __align__(16) float g_x[NN * DD];
__device__ __align__(16) float g_h[NN * DD];
__device__ __align__(16) float g_agg[NN * DD];
__device__ __align__(16) float g_Z[3][NN * DD];
__device__ __align__(16) float g_stats[2 * DD];
__device__ __align__(16) float g_pool[GG * DD];
// CSR scratch
__device__ int g_cnt[NN];
__device__ int g_sc[NN];
__device__ int g_bsum[128];
__device__ int g_off[NN + 1];
__device__ int g_cur[NN];
__device__ int g_csr[EE];

__device__ __forceinline__ void red_add_v2(float* p, float a, float b) {
    asm volatile("red.global.add.v2.f32 [%0], {%1, %2};"
                 :: "l"(p), "f"(a), "f"(b) : "memory");
}

// split bf16: h = bf16(f), l = bf16(f - h); packed as bf16x2
__device__ __forceinline__ void pack2(float f0, float f1, uint32_t& h, uint32_t& l) {
    __nv_bfloat162 hb;
    hb.x = __float2bfloat16_rn(f0);
    hb.y = __float2bfloat16_rn(f1);
    __nv_bfloat162 lb;
    lb.x = __float2bfloat16_rn(f0 - __bfloat162float(hb.x));
    lb.y = __float2bfloat16_rn(f1 - __bfloat162float(hb.y));
    h = *reinterpret_cast<uint32_t*>(&hb);
    l = *reinterpret_cast<uint32_t*>(&lb);
}

__device__ __forceinline__ void mma_bf16(float* d, uint32_t a0, uint32_t a1,
                                         uint32_t a2, uint32_t a3,
                                         uint32_t b0, uint32_t b1) {
    asm volatile("mma.sync.aligned.m16n8k16.row.col.f32.bf16.bf16.f32 "
                 "{%0,%1,%2,%3}, {%4,%5,%6,%7}, {%8,%9}, {%0,%1,%2,%3};"
                 : "+f"(d[0]), "+f"(d[1]), "+f"(d[2]), "+f"(d[3])
                 : "r"(a0), "r"(a1), "r"(a2), "r"(a3), "r"(b0), "r"(b1));
}

// As layout: [wt(8)][kstep(4)][lane(32)][8 u32] = 8192 u32 (32KB)
__device__ __forceinline__ void pack_A(uint32_t* As, int r, int cq, float4 v) {
    int wt = r >> 4;
    int ri = r & 15;
    int k0 = cq * 4;
    int ks = k0 >> 4;
    int ki = k0 & 15;
    int reg = (ri >> 3) + ((ki >> 3) << 1);
    int lane0 = ((ri & 7) << 2) | ((ki >> 1) & 3);
    uint32_t h0, l0, h1, l1;
    pack2(v.x, v.y, h0, l0);
    pack2(v.z, v.w, h1, l1);
    uint32_t* p0 = As + ((wt * 4 + ks) * 32 + lane0) * 8 + reg;
    p0[0] = h0;
    p0[4] = l0;
    p0[8] = h1;
    p0[12] = l1;
}

// Wsp layout: [kstep(4)][nt(8)][lane(32)][4 u32] = 4096 u32 (16KB)
__device__ __forceinline__ void pack_W(uint32_t* Wsp, int k2, int n, float w0, float w1) {
    int ks = k2 >> 3;
    int p = k2 & 7;
    int tid4 = p & 3;
    int bsel = p >> 2;
    int lane = ((n & 7) << 2) | tid4;
    int nt = n >> 3;
    uint32_t h, l;
    pack2(w0, w1, h, l);
    uint32_t* q = Wsp + ((ks * 8 + nt) * 32 + lane) * 4;
    q[bsel] = h;
    q[2 + bsel] = l;
}

// d[8][4] += A(16x64) * W(64x64), 3-term split-bf16
__device__ __forceinline__ void mma_main(const uint32_t* As, const uint32_t* Wsp,
                                         int wid, int lane, float d[8][4]) {
#pragma unroll
    for (int ks = 0; ks < 4; ks++) {
        const uint32_t* ap = As + ((wid * 4 + ks) * 32 + lane) * 8;
        uint4 AH = *(const uint4*)ap;
        uint4 AL = *(const uint4*)(ap + 4);
        const uint32_t* wp = Wsp + (ks * 256 + lane) * 4;
#pragma unroll
        for (int nt = 0; nt < 8; nt++) {
            uint4 B = *(const uint4*)(wp + nt * 128);
            mma_bf16(d[nt], AH.x, AH.y, AH.z, AH.w, B.x, B.y);
            mma_bf16(d[nt], AH.x, AH.y, AH.z, AH.w, B.z, B.w);
            mma_bf16(d[nt], AL.x, AL.y, AL.z, AL.w, B.x, B.y);
        }
    }
}

// accumulators -> tile[128][64] f32 (tile aliases As)
__device__ __forceinline__ void mma_scatter(float* tile, int wid, int lane, float d[8][4]) {
    int g = lane >> 2;
    int tq = lane & 3;
    int r0 = wid * 16 + g;
#pragma unroll
    for (int nt = 0; nt < 8; nt++) {
        int c = nt * 8 + tq * 2;
        *(float2*)&tile[r0 * 64 + c] = make_float2(d[nt][0], d[nt][1]);
        *(float2*)&tile[(r0 + 8) * 64 + c] = make_float2(d[nt][2], d[nt][3]);
    }
}

// ---------------- GEMM 0 (also zeros pool/stats; cnt zeroed on side stream) ----------------
__global__ __launch_bounds__(256, 3) void k_gemm0(const float* __restrict__ xin,
                                                  const float* __restrict__ W0,
                                                  const float* __restrict__ b0) {
    __shared__ __align__(16) uint32_t As[8192];
    __shared__ __align__(16) uint32_t Wsp[4096];
    float* tile = (float*)As;
    int t = threadIdx.x;
    int lane = t & 31;
    int wid = t >> 5;
    int R0 = blockIdx.x * TR;
    float4 z4 = make_float4(0.f, 0.f, 0.f, 0.f);

    if (blockIdx.x < 32) ((float4*)g_pool)[blockIdx.x * 256u + t] = z4;
    if (blockIdx.x == 0 && t < 128) g_stats[t] = 0.f;

    float d[8][4] = {};
    for (int kb = 0; kb < 128; kb += 64) {
        if (kb) __syncthreads();
#pragma unroll
        for (int i = 0; i < 8; i++) {
            int idx4 = t + i * 256;
            int r = idx4 >> 4;
            int cq = idx4 & 15;
            int gr = R0 + r;
            float4 v = (gr < NN) ? *(const float4*)&xin[gr * 128 + kb + cq * 4] : z4;
            pack_A(As, r, cq, v);
        }
#pragma unroll
        for (int i = 0; i < 8; i++) {
            int pidx = t + i * 256;
            int k2 = pidx >> 6;
            int n = pidx & 63;
            int gk = kb + 2 * k2;
            pack_W(Wsp, k2, n, W0[gk * 64 + n], W0[(gk + 1) * 64 + n]);
        }
        __syncthreads();
        mma_main(As, Wsp, wid, lane, d);
    }
    mma_scatter(tile, wid, lane, d);
    __syncthreads();

    int tx = t & 15;
    int ty = t >> 4;
    int c4 = tx * 4;
    float4 bb = *(const float4*)&b0[c4];
    float o[8][4];
    float pr[8];
#pragma unroll
    for (int r = 0; r < 8; r++) {
        float4 dv = *(const float4*)&tile[(ty * 8 + r) * 64 + c4];
        o[r][0] = fmaxf(dv.x + bb.x, 0.f);
        o[r][1] = fmaxf(dv.y + bb.y, 0.f);
        o[r][2] = fmaxf(dv.z + bb.z, 0.f);
        o[r][3] = fmaxf(dv.w + bb.w, 0.f);
        pr[r] = o[r][0]*o[r][0] + o[r][1]*o[r][1] + o[r][2]*o[r][2] + o[r][3]*o[r][3];
    }
#pragma unroll
    for (int m = 1; m < 16; m <<= 1) {
#pragma unroll
        for (int r = 0; r < 8; r++) pr[r] += __shfl_xor_sync(0xffffffffu, pr[r], m);
    }
#pragma unroll
    for (int r = 0; r < 8; r++) {
        int gr = R0 + ty * 8 + r;
        if (gr < NN) {
            float4 ov = make_float4(o[r][0], o[r][1], o[r][2], o[r][3]);
            *(float4*)&g_x[gr * 64 + c4] = ov;
            float cn = fmaxf(sqrtf(pr[r]), 1e-15f);
            float f = (cn > 0.996f) ? (0.996f / cn) : 1.0f;
            f *= SCALING_F;
            *(float4*)&g_Z[0][gr * 64 + c4] =
                make_float4(o[r][0]*f, o[r][1]*f, o[r][2]*f, o[r][3]*f);
        }
    }
}

// ---------------- CSR build (side stream) ----------------
__global__ void k_zero_cnt() {
    int i = blockIdx.x * 256 + threadIdx.x;
    if (i < NN) g_cnt[i] = 0;
}

__global__ void k_hist(const int* __restrict__ ei) {
    unsigned e = blockIdx.x * 256u + threadIdx.x;
    if (e < EE) atomicAdd(&g_cnt[__ldg(&ei[EE + e])], 1);
}

__global__ void k_scan1() {
    __shared__ int ws[16];
    int t = threadIdx.x;
    int b = blockIdx.x;
    int i = b * 512 + t;
    int lane = t & 31;
    int w = t >> 5;
    int x = (i < NN) ? g_cnt[i] : 0;
#pragma unroll
    for (int o = 1; o < 32; o <<= 1) {
        int y = __shfl_up_sync(0xffffffffu, x, o);
        if (lane >= o) x += y;
    }
    if (lane == 31) ws[w] = x;
    __syncthreads();
    if (w == 0) {
        int s = (lane < 16) ? ws[lane] : 0;
#pragma unroll
        for (int o = 1; o < 16; o <<= 1) {
            int y = __shfl_up_sync(0xffffffffu, s, o);
            if (lane >= o) s += y;
        }
        if (lane < 16) ws[lane] = s;
    }
    __syncthreads();
    int incl = x + (w ? ws[w - 1] : 0);
    if (i < NN) g_sc[i] = incl;
    if (t == 511) g_bsum[b] = incl;
}

__global__ void k_scan2() {
    __shared__ int ws[4];
    int t = threadIdx.x;
    int lane = t & 31;
    int w = t >> 5;
    int x = (t < NB) ? g_bsum[t] : 0;
#pragma unroll
    for (int o = 1; o < 32; o <<= 1) {
        int y = __shfl_up_sync(0xffffffffu, x, o);
        if (lane >= o) x += y;
    }
    if (lane == 31) ws[w] = x;
    __syncthreads();
    if (w == 0 && lane < 4) {
        int s = ws[lane];
#pragma unroll
        for (int o = 1; o < 4; o <<= 1) {
            int y = __shfl_up_sync(0x0000000fu, s, o);
            if (lane >= o) s += y;
        }
        ws[lane] = s;
    }
    __syncthreads();
    int incl = x + (w ? ws[w - 1] : 0);
    if (t < NB) g_bsum[t] = incl;
}

__global__ void k_scan3() {
    int b = blockIdx.x;
    int i = b * 512 + threadIdx.x;
    if (i < NN) {
        int base = (b > 0) ? g_bsum[b - 1] : 0;
        int incl = g_sc[i] + base;
        g_off[i + 1] = incl;
        g_cur[i] = incl - g_cnt[i];
        if (i == 0) g_off[0] = 0;
    }
}

__global__ void k_fill(const int* __restrict__ ei) {
    unsigned e = blockIdx.x * 256u + threadIdx.x;
    if (e < EE) {
        int dd = __ldg(&ei[EE + e]);
        int ss = __ldg(&ei[e]);
        int slot = atomicAdd(&g_cur[dd], 1);
        g_csr[slot] = ss;
    }
}

// ---------------- gather: agg[d] = x[d] + sum_{s in N(d)} x[s] ----------------
__global__ __launch_bounds__(256, 8) void k_gather() {
    int t = threadIdx.x;
    if (blockIdx.x == 0 && t < 128) g_stats[t] = 0.f;
    int gw = (blockIdx.x * 256 + t) >> 5;
    if (gw >= NN) return;
    int lane = t & 31;
    int q = lane & 15;
    int grp = lane >> 4;
    int o0 = g_off[gw];
    int o1 = g_off[gw + 1];
    float4 acc = make_float4(0.f, 0.f, 0.f, 0.f);
#pragma unroll 2
    for (int j = o0 + grp; j < o1; j += 2) {
        int s = __ldg(&g_csr[j]);
        float4 v = *(const float4*)&g_x[(unsigned)s * 64u + q * 4u];
        acc.x += v.x;
        acc.y += v.y;
        acc.z += v.z;
        acc.w += v.w;
    }
    acc.x += __shfl_xor_sync(0xffffffffu, acc.x, 16);
    acc.y += __shfl_xor_sync(0xffffffffu, acc.y, 16);
    acc.z += __shfl_xor_sync(0xffffffffu, acc.z, 16);
    acc.w += __shfl_xor_sync(0xffffffffu, acc.w, 16);
    if (lane < 16) {
        float4 xv = *(const float4*)&g_x[(unsigned)gw * 64u + q * 4u];
        *(float4*)&g_agg[(unsigned)gw * 64u + q * 4u] =
            make_float4(xv.x + acc.x, xv.y + acc.y, xv.z + acc.z, xv.w + acc.w);
    }
}

// ---------------- GEMM A (stats buffers alias Wsp after mma) ----------------
__global__ __launch_bounds__(256, 3) void k_gemmA(const float* __restrict__ W,
                                                  const float* __restrict__ b) {
    __shared__ __align__(16) uint32_t As[8192];
    __shared__ __align__(16) uint32_t Wsp[4096];
    float* tile = (float*)As;
    float* s_sum = (float*)Wsp;
    float* s_sq = (float*)Wsp + 64;
    int t = threadIdx.x;
    int lane = t & 31;
    int wid = t >> 5;
    int R0 = blockIdx.x * TR;
    float4 z4 = make_float4(0.f, 0.f, 0.f, 0.f);

#pragma unroll
    for (int i = 0; i < 8; i++) {
        int idx4 = t + i * 256;
        int r = idx4 >> 4;
        int cq = idx4 & 15;
        int gr = R0 + r;
        float4 v = (gr < NN) ? *(const float4*)&g_agg[gr * 64 + cq * 4] : z4;
        pack_A(As, r, cq, v);
    }
#pragma unroll
    for (int i = 0; i < 8; i++) {
        int pidx = t + i * 256;
        int k2 = pidx >> 6;
        int n = pidx & 63;
        pack_W(Wsp, k2, n, W[2 * k2 * 64 + n], W[(2 * k2 + 1) * 64 + n]);
    }
    __syncthreads();
    float d[8][4] = {};
    mma_main(As, Wsp, wid, lane, d);
    mma_scatter(tile, wid, lane, d);
    __syncthreads();
    if (t < 64) { s_sum[t] = 0.f; s_sq[t] = 0.f; }
    __syncthreads();

    int tx = t & 15;
    int ty = t >> 4;
    int c4 = tx * 4;
    float4 bb = *(const float4*)&b[c4];
    float ps[4] = {0.f, 0.f, 0.f, 0.f};
    float pq[4] = {0.f, 0.f, 0.f, 0.f};
#pragma unroll
    for (int i = 0; i < 8; i++) {
        int gr = R0 + ty * 8 + i;
        float4 dv = *(const float4*)&tile[(ty * 8 + i) * 64 + c4];
        float o0 = fmaxf(dv.x + bb.x, 0.f);
        float o1 = fmaxf(dv.y + bb.y, 0.f);
        float o2 = fmaxf(dv.z + bb.z, 0.f);
        float o3 = fmaxf(dv.w + bb.w, 0.f);
        if (gr < NN) {
            *(float4*)&g_h[gr * 64 + c4] = make_float4(o0, o1, o2, o3);
            ps[0] += o0; ps[1] += o1; ps[2] += o2; ps[3] += o3;
            pq[0] += o0*o0; pq[1] += o1*o1; pq[2] += o2*o2; pq[3] += o3*o3;
        }
    }
#pragma unroll
    for (int j = 0; j < 4; j++) {
        atomicAdd(&s_sum[c4 + j], ps[j]);
        atomicAdd(&s_sq[c4 + j], pq[j]);
    }
    __syncthreads();
    if (t < 64) {
        atomicAdd(&g_stats[t], s_sum[t]);
        atomicAdd(&g_stats[64 + t], s_sq[t]);
    }
}

// ---------------- GEMM B + hyperbolic update (BN affine in registers) ----------------
__global__ __launch_bounds__(256, 3) void k_gemmB(const float* __restrict__ W,
                                                  const float* __restrict__ b,
                                                  const float* __restrict__ gamma,
                                                  const float* __restrict__ beta,
                                                  const int* __restrict__ batch,
                                                  int iter, int last) {
    __shared__ __align__(16) uint32_t As[8192];
    __shared__ __align__(16) uint32_t Wsp[4096];
    float* tile = (float*)As;
    int t = threadIdx.x;
    int lane = t & 31;
    int wid = t >> 5;
    int R0 = blockIdx.x * TR;
    int tx = t & 15;
    int ty = t >> 4;
    int c4 = tx * 4;

    float scr[4], shr[4];
#pragma unroll
    for (int j = 0; j < 4; j++) {
        int c = c4 + j;
        float mean = g_stats[c] * (1.0f / NN);
        float var = g_stats[64 + c] * (1.0f / NN) - mean * mean;
        float inv = rsqrtf(var + 1e-5f);
        float s = gamma[c] * inv;
        scr[j] = s;
        shr[j] = beta[c] - mean * s;
    }

#pragma unroll
    for (int i = 0; i < 8; i++) {
        int idx4 = t + i * 256;
        int r = idx4 >> 4;
        int cq = idx4 & 15;
        int gr = R0 + r;
        float4 v;
        if (gr < NN) {
            float4 h = *(const float4*)&g_h[gr * 64 + cq * 4];
            v.x = fmaf(h.x, scr[0], shr[0]);
            v.y = fmaf(h.y, scr[1], shr[1]);
            v.z = fmaf(h.z, scr[2], shr[2]);
            v.w = fmaf(h.w, scr[3], shr[3]);
        } else {
            v = make_float4(0.f, 0.f, 0.f, 0.f);
        }
        pack_A(As, r, cq, v);
    }
#pragma unroll
    for (int i = 0; i < 8; i++) {
        int pidx = t + i * 256;
        int k2 = pidx >> 6;
        int n = pidx & 63;
        pack_W(Wsp, k2, n, W[2 * k2 * 64 + n], W[(2 * k2 + 1) * 64 + n]);
    }
    __syncthreads();
    float d[8][4] = {};
    mma_main(As, Wsp, wid, lane, d);
    mma_scatter(tile, wid, lane, d);
    __syncthreads();

    float4 bb = *(const float4*)&b[c4];
#pragma unroll
    for (int i = 0; i < 8; i++) {
        int r = ty * 8 + i;
        int gr = R0 + r;
        float4 dv = *(const float4*)&tile[r * 64 + c4];
        float4 ov;
        ov.x = fmaxf(dv.x + bb.x, 0.f);
        ov.y = fmaxf(dv.y + bb.y, 0.f);
        ov.z = fmaxf(dv.z + bb.z, 0.f);
        ov.w = fmaxf(dv.w + bb.w, 0.f);
        if (c4 == 60) ov.w = 0.f;    // x[:, -1] = 0
        *(float4*)&tile[r * 64 + c4] = ov;
        if (gr < NN) {
            *(float4*)&g_x[gr * 64 + c4] = ov;
        }
    }
    __syncthreads();

    // hyperbolic update, closed form: zn = cx*x + cpp*pp + cmm*mc + ce*e63
    const float2* zc2 = (const float2*)g_Z[iter];
    const float2* zp2 = (const float2*)g_Z[(iter + 2) % 3];
    float2* zn2 = (float2*)g_Z[(iter + 1) % 3];

    for (int i = 0; i < 16; i++) {
        int rr = wid * 16 + i;
        int gr = R0 + rr;
        if (gr >= NN) break;
        int off = gr * 32 + lane;
        float2 xv = *(const float2*)&tile[rr * 64 + lane * 2];
        float2 mc = zc2[off];
        float2 pp = (iter == 0) ? make_float2(0.f, 0.f) : zp2[off];

        float d0 = xv.x*xv.x + xv.y*xv.y;
        float d1 = mc.x*mc.x + mc.y*mc.y;
        float d2 = pp.x*pp.x + pp.y*pp.y;
        float d3 = pp.x*mc.x + pp.y*mc.y;
        float d4 = pp.x*xv.x + pp.y*xv.y;
        float d5 = mc.x*xv.x + mc.y*xv.y;
#pragma unroll
        for (int o = 16; o; o >>= 1) {
            d0 += __shfl_xor_sync(0xffffffffu, d0, o);
            d1 += __shfl_xor_sync(0xffffffffu, d1, o);
            d2 += __shfl_xor_sync(0xffffffffu, d2, o);
            d3 += __shfl_xor_sync(0xffffffffu, d3, o);
            d4 += __shfl_xor_sync(0xffffffffu, d4, o);
            d5 += __shfl_xor_sync(0xffffffffu, d5, o);
        }
        float mc63 = __shfl_sync(0xffffffffu, mc.y, 31);
        float pp63 = __shfl_sync(0xffffffffu, pp.y, 31);

        float cn = fmaxf(sqrtf(d0), 1e-15f);
        float f = (cn > 0.996f) ? (0.996f / cn) : 1.0f;
        f *= SCALING_F;
        float mn2 = fmaxf(d1, 1e-15f);
        float im = 1.0f / mn2;
        float a2 = d1 * im * im;
        float r2 = a2 - 1.0f;
        float un2 = fmaxf(d2 - 2.0f*d3*im + a2, 1e-15f);
        float s1 = r2 / un2;
        float t1 = 1.0f - s1;
        float zpn2 = s1*s1*d2 + 2.0f*s1*t1*d3*im + t1*t1*a2;
        float pn = fmaxf(sqrtf(zpn2), 1e-15f);
        float zpzc = f * (s1*d4 + t1*d5*im);
        float zp63 = s1*pp63 + t1*mc63*im;
        float mnum = -zpzc / pn;
        float mden = 2.0f - 2.0f*zp63/pn;
        float mm = mnum / mden;
        float gg = 2.0f*mm/pn;
        float zcc2 = f*f*d0 + gg*gg*zpn2 + 4.0f*mm*mm + 2.0f*gg*zpzc - 4.0f*mm*gg*zp63;
        float zca = f*d5*im;
        float zpa = s1*d3*im + t1*a2;
        float zcca = zca + gg*zpa - 2.0f*mm*mc63*im;
        float u2n = fmaxf(zcc2 - 2.0f*zcca + a2, 1e-15f);
        float s2 = r2 / u2n;
        float t2 = 1.0f - s2;
        float cx = s2*f;
        float cpp = s2*gg*s1;
        float cmm = (s2*gg*t1 + t2)*im;
        float ce = -2.0f*mm*s2;

        float znx = cx*xv.x + cpp*pp.x + cmm*mc.x;
        float zny = cx*xv.y + cpp*pp.y + cmm*mc.y;
        if (lane == 31) zny += ce;
        zn2[off] = make_float2(znx, zny);

        if (last) {
            float znn2 = s2*s2*zcc2 + 2.0f*s2*t2*zcca + t2*t2*a2;
            float yn = fmaxf(sqrtf(fmaxf(znn2, 0.f)), 1e-15f);
            float tt = fminf(yn, 1.0f);
            float sc = atanhf(tt) / yn;
            int bg = __ldg(&batch[gr]);
            red_add_v2(&g_pool[bg * 64 + lane * 2], znx * sc, zny * sc);
        }
    }
}

// ---------------- head MLP + log_softmax ----------------
__global__ void k_head(const float* __restrict__ fc1W, const float* __restrict__ fc1b,
                       const float* __restrict__ fc2W, const float* __restrict__ fc2b,
                       const float* __restrict__ fc3W, const float* __restrict__ fc3b,
                       float* __restrict__ out) {
    __shared__ float sp[64];
    __shared__ float h1[128];
    __shared__ float h2[64];
    __shared__ float lo[10];
    int g = blockIdx.x;
    int t = threadIdx.x;
    if (t < 64) sp[t] = g_pool[g * 64 + t];
    __syncthreads();
    {
        float acc = fc1b[t];
#pragma unroll 8
        for (int k = 0; k < 64; k++) acc = fmaf(sp[k], fc1W[k * 128 + t], acc);
        h1[t] = fmaxf(acc, 0.f);
    }
    __syncthreads();
    if (t < 64) {
        float acc = fc2b[t];
#pragma unroll 8
        for (int k = 0; k < 128; k++) acc = fmaf(h1[k], fc2W[k * 64 + t], acc);
        h2[t] = fmaxf(acc, 0.f);
    }
    __syncthreads();
    if (t < 10) {
        float acc = fc3b[t];
#pragma unroll 8
        for (int k = 0; k < 64; k++) acc = fmaf(h2[k], fc3W[k * 10 + t], acc);
        lo[t] = acc;
    }
    __syncthreads();
    if (t == 0) {
        float mx = lo[0];
#pragma unroll
        for (int c = 1; c < 10; c++) mx = fmaxf(mx, lo[c]);
        float s = 0.f;
#pragma unroll
        for (int c = 0; c < 10; c++) s += expf(lo[c] - mx);
        float lse = mx + logf(s);
#pragma unroll
        for (int c = 0; c < 10; c++) out[g * 10 + c] = lo[c] - lse;
    }
}

// ---------------- launch (CSR build forked onto side stream) ----------------
extern "C" void kernel_launch(void* const* d_in, const int* in_sizes, int n_in,
                              void* d_out, int out_size) {
    const float* x     = (const float*)d_in[0];
    const int*   ei    = (const int*)d_in[1];
    const int*   batch = (const int*)d_in[2];
    const float* W0    = (const float*)d_in[3];
    const float* b0    = (const float*)d_in[4];
    const float* cW1   = (const float*)d_in[5];
    const float* cb1   = (const float*)d_in[6];
    const float* gamma = (const float*)d_in[7];
    const float* beta  = (const float*)d_in[8];
    const float* cW2   = (const float*)d_in[9];
    const float* cb2   = (const float*)d_in[10];
    const float* fc1W  = (const float*)d_in[11];
    const float* fc1b  = (const float*)d_in[12];
    const float* fc2W  = (const float*)d_in[13];
    const float* fc2b  = (const float*)d_in[14];
    const float* fc3W  = (const float*)d_in[15];
    const float* fc3b  = (const float*)d_in[16];
    float* out = (float*)d_out;

    // lazy one-time stream/event creation (first call is the non-captured
    // correctness run; capture calls reuse the same handles)
    static cudaStream_t s2 = nullptr;
    static cudaEvent_t evFork = nullptr, evJoin = nullptr;
    if (s2 == nullptr) {
        cudaStreamCreateWithFlags(&s2, cudaStreamNonBlocking);
        cudaEventCreateWithFlags(&evFork, cudaEventDisableTiming);
        cudaEventCreateWithFlags(&evJoin, cudaEventDisableTiming);
    }

    const int gemmGrid = (NN + TR - 1) / TR;        // 391
    const int eGrid = (EE + 255) / 256;             // 3125
    const int zGrid = (NN + 255) / 256;             // 196
    const int gatherGrid = (NN * 32 + 255) / 256;   // 6250

    // fork: side stream builds CSR while main stream runs gemm0
    cudaEventRecord(evFork, 0);
    cudaStreamWaitEvent(s2, evFork, 0);

    k_zero_cnt<<<zGrid, 256, 0, s2>>>();
    k_hist<<<eGrid, 256, 0, s2>>>(ei);
    k_scan1<<<NB, 512, 0, s2>>>();
    k_scan2<<<1, 128, 0, s2>>>();
    k_scan3<<<NB, 512, 0, s2>>>();
    k_fill<<<eGrid, 256, 0, s2>>>(ei);
    cudaEventRecord(evJoin, s2);

    k_gemm0<<<gemmGrid, 256>>>(x, W0, b0);

    // join: gather needs both g_x (main) and CSR (side)
    cudaStreamWaitEvent(0, evJoin, 0);

    for (int l = 0; l < 3; l++) {
        k_gather<<<gatherGrid, 256>>>();
        k_gemmA<<<gemmGrid, 256>>>(cW1 + l * 64 * 64, cb1 + l * 64);
        k_gemmB<<<gemmGrid, 256>>>(cW2 + l * 64 * 64, cb2 + l * 64,
                                   gamma + l * 64, beta + l * 64,
                                   batch, l, (l == 2) ? 1 : 0);
    }
    k_head<<<512, 128>>>(fc1W, fc1b, fc2W, fc2b, fc3W, fc3b, out);
}